// round 6
// baseline (speedup 1.0000x reference)
#include <cuda_runtime.h>
#include <cuda_bf16.h>
#include <cstdint>
#include <cstddef>

#define HD        2048
#define SEQ       8192
#define IN_DIM    16
#define NCTA      147
#define JCAP      14              // hidden units per CTA (last CTA gets 4)
#define WARPS     14
#define TPB       (WARPS * 32)    // 448 threads
#define SMEM_COLS 1536            // weight columns kept in smem (k-chunks 0..11)
#define REG_K0    12              // k-chunks 12..15 register-resident
#define W_ROW_B   (SMEM_COLS * 2) // 3072 bytes per bf16 weight row
#define SMEM_BYTES (HD * 4 + 256 + 56 * W_ROW_B)   // 8192 + 256 + 172032 = 180480

// Persistent scratch (static __device__ globals — no allocation APIs).
__device__ float d_hs[(size_t)(SEQ + 1) * HD];  // h history, row 0 == h_0 == 0
__device__ int   d_flags[NCTA];                 // last completed step per CTA

__device__ __forceinline__ float blo(unsigned u) { return __uint_as_float(u << 16); }
__device__ __forceinline__ float bhi(unsigned u) { return __uint_as_float(u & 0xffff0000u); }

__device__ __forceinline__ int ld_acq(const int* p) {
    int v;
    asm volatile("ld.acquire.gpu.global.b32 %0, [%1];" : "=r"(v) : "l"(p));
    return v;
}
__device__ __forceinline__ void st_rel(int* p, int v) {
    asm volatile("st.release.gpu.global.b32 [%0], %1;" :: "l"(p), "r"(v) : "memory");
}

__device__ __forceinline__ float sigmoidf_(float x) {
    return 1.0f / (1.0f + __expf(-x));
}

// ---------------------------------------------------------------------------
// Persistent LSTM recurrence. CTA b owns hidden units [b*14, b*14+J).
// Its 4J gate rows of W_hh live on-chip (bf16): cols [0,1536) in SMEM,
// cols [1536,2048) in registers. h is staged fp32 in SMEM each step.
// Gate order (PyTorch): i, f, g, o  ->  local row r = g*J + jj.
// ---------------------------------------------------------------------------
extern "C" __global__ void __launch_bounds__(TPB, 1)
lstm_persist(const float* __restrict__ sa,  const float* __restrict__ Wih,
             const float* __restrict__ Whh, const float* __restrict__ bih,
             const float* __restrict__ bhh)
{
    extern __shared__ unsigned char smem[];
    float*          h_sm = (float*)smem;                       // 2048 f32
    float*          gbuf = (float*)(smem + HD * 4);            // 64 f32 gate staging
    __nv_bfloat16*  w_sm = (__nv_bfloat16*)(smem + HD * 4 + 256);

    const int tid  = threadIdx.x;
    const int w    = tid >> 5;
    const int lane = tid & 31;
    const int b    = blockIdx.x;
    const int j0   = b * JCAP;
    const int J    = (b == NCTA - 1) ? (HD - (NCTA - 1) * JCAP) : JCAP;  // 14 or 4
    const int R    = 4 * J;                                    // gate rows this CTA
    const int r0   = 4 * w;                                    // this warp's first local row
    const bool act = (r0 < R);

    // ---- one-time init: stage bf16 weights into SMEM (cols [0,1536)) ----
    for (int idx = tid; idx < R * SMEM_COLS; idx += TPB) {
        int r   = idx / SMEM_COLS;
        int col = idx - r * SMEM_COLS;
        int gr  = (r / J) * HD + j0 + (r % J);                 // global gate row
        w_sm[r * SMEM_COLS + col] = __float2bfloat16(Whh[(size_t)gr * HD + col]);
    }

    // ---- one-time init: register weights (cols [1536,2048)), xproj, biases ----
    unsigned wreg[4][4][2];
    float    wih_a = 0.f, wih_b = 0.f;
    float    bias0 = 0.f, bias1 = 0.f, bias2 = 0.f, bias3 = 0.f;
    #pragma unroll
    for (int i = 0; i < 4; ++i)
        #pragma unroll
        for (int k = 0; k < 4; ++k) { wreg[i][k][0] = 0u; wreg[i][k][1] = 0u; }

    if (act) {
        #pragma unroll
        for (int i = 0; i < 4; ++i) {
            int r  = r0 + i;
            int gr = (r / J) * HD + j0 + (r % J);
            const float* wr = Whh + (size_t)gr * HD;
            #pragma unroll
            for (int k = 0; k < 4; ++k) {
                int c = 4 * lane + 128 * (REG_K0 + k);
                __nv_bfloat162 p0 = __floats2bfloat162_rn(wr[c + 0], wr[c + 1]);
                __nv_bfloat162 p1 = __floats2bfloat162_rn(wr[c + 2], wr[c + 3]);
                wreg[i][k][0] = *(unsigned*)&p0;   // low 16 bits = even col
                wreg[i][k][1] = *(unsigned*)&p1;
            }
            float bi = __ldg(bih + gr) + __ldg(bhh + gr);
            if (i == 0) bias0 = bi; else if (i == 1) bias1 = bi;
            else if (i == 2) bias2 = bi; else bias3 = bi;
        }
        // x_proj coefficients: lanes 0..15 -> rows r0, r0+2 ; lanes 16..31 -> rows r0+1, r0+3
        int half = lane >> 4, m = lane & 15;
        int ra = r0 + half, rb = r0 + 2 + half;
        int gra = (ra / J) * HD + j0 + (ra % J);
        int grb = (rb / J) * HD + j0 + (rb % J);
        wih_a = __ldg(Wih + (size_t)gra * IN_DIM + m);
        wih_b = __ldg(Wih + (size_t)grb * IN_DIM + m);
    }

    // Per-row SMEM weight base pointers (lane-offset folded in).
    const uint2* wrow0 = (const uint2*)((const char*)w_sm + (size_t)(r0 + 0) * W_ROW_B + 8 * lane);
    const uint2* wrow1 = (const uint2*)((const char*)w_sm + (size_t)(r0 + 1) * W_ROW_B + 8 * lane);
    const uint2* wrow2 = (const uint2*)((const char*)w_sm + (size_t)(r0 + 2) * W_ROW_B + 8 * lane);
    const uint2* wrow3 = (const uint2*)((const char*)w_sm + (size_t)(r0 + 3) * W_ROW_B + 8 * lane);

    float c_st = 0.0f;   // cell state for unit (j0 + tid), threads tid < J

    for (int t = 0; t < SEQ; ++t) {
        // -- wait until every CTA has published h_t (flags >= t-1; reset kernel set -1) --
        if (tid < NCTA) { while (ld_acq(&d_flags[tid]) < t - 1) { } }
        __syncthreads();

        // -- stage h_t into SMEM (fp32, L2-coherent loads) --
        {
            const float4* hrow = (const float4*)(d_hs + (size_t)t * HD);
            for (int i = tid; i < HD / 4; i += TPB)
                ((float4*)h_sm)[i] = __ldcg(hrow + i);
        }
        __syncthreads();

        if (act) {
            float a0 = 0.f, a1 = 0.f, a2 = 0.f, a3 = 0.f;
            const float4* h4 = (const float4*)h_sm;

            #pragma unroll
            for (int k = 0; k < REG_K0; ++k) {           // SMEM weight chunks
                float4 hv = h4[lane + 32 * k];
                uint2 p;
                p = wrow0[32 * k];
                a0 = fmaf(blo(p.x), hv.x, a0); a0 = fmaf(bhi(p.x), hv.y, a0);
                a0 = fmaf(blo(p.y), hv.z, a0); a0 = fmaf(bhi(p.y), hv.w, a0);
                p = wrow1[32 * k];
                a1 = fmaf(blo(p.x), hv.x, a1); a1 = fmaf(bhi(p.x), hv.y, a1);
                a1 = fmaf(blo(p.y), hv.z, a1); a1 = fmaf(bhi(p.y), hv.w, a1);
                p = wrow2[32 * k];
                a2 = fmaf(blo(p.x), hv.x, a2); a2 = fmaf(bhi(p.x), hv.y, a2);
                a2 = fmaf(blo(p.y), hv.z, a2); a2 = fmaf(bhi(p.y), hv.w, a2);
                p = wrow3[32 * k];
                a3 = fmaf(blo(p.x), hv.x, a3); a3 = fmaf(bhi(p.x), hv.y, a3);
                a3 = fmaf(blo(p.y), hv.z, a3); a3 = fmaf(bhi(p.y), hv.w, a3);
            }
            #pragma unroll
            for (int k = 0; k < 4; ++k) {                // register weight chunks
                float4 hv = h4[lane + 32 * (REG_K0 + k)];
                unsigned u, v;
                u = wreg[0][k][0]; v = wreg[0][k][1];
                a0 = fmaf(blo(u), hv.x, a0); a0 = fmaf(bhi(u), hv.y, a0);
                a0 = fmaf(blo(v), hv.z, a0); a0 = fmaf(bhi(v), hv.w, a0);
                u = wreg[1][k][0]; v = wreg[1][k][1];
                a1 = fmaf(blo(u), hv.x, a1); a1 = fmaf(bhi(u), hv.y, a1);
                a1 = fmaf(blo(v), hv.z, a1); a1 = fmaf(bhi(v), hv.w, a1);
                u = wreg[2][k][0]; v = wreg[2][k][1];
                a2 = fmaf(blo(u), hv.x, a2); a2 = fmaf(bhi(u), hv.y, a2);
                a2 = fmaf(blo(v), hv.z, a2); a2 = fmaf(bhi(v), hv.w, a2);
                u = wreg[3][k][0]; v = wreg[3][k][1];
                a3 = fmaf(blo(u), hv.x, a3); a3 = fmaf(bhi(u), hv.y, a3);
                a3 = fmaf(blo(v), hv.z, a3); a3 = fmaf(bhi(v), hv.w, a3);
            }

            // x_proj for this warp's 4 rows (exact fp32): half-warp reductions
            float sv = __ldg(sa + (size_t)t * IN_DIM + (lane & 15));
            float va = wih_a * sv, vb = wih_b * sv;
            #pragma unroll
            for (int m = 1; m <= 8; m <<= 1) {
                va += __shfl_xor_sync(0xffffffffu, va, m);
                vb += __shfl_xor_sync(0xffffffffu, vb, m);
            }
            a0 += (lane == 0)  ? va : 0.f;   // row r0   xproj (lanes 0..15 group)
            a1 += (lane == 16) ? va : 0.f;   // row r0+1 xproj (lanes 16..31 group)
            a2 += (lane == 0)  ? vb : 0.f;   // row r0+2
            a3 += (lane == 16) ? vb : 0.f;   // row r0+3

            #pragma unroll
            for (int m = 16; m >= 1; m >>= 1) {
                a0 += __shfl_xor_sync(0xffffffffu, a0, m);
                a1 += __shfl_xor_sync(0xffffffffu, a1, m);
                a2 += __shfl_xor_sync(0xffffffffu, a2, m);
                a3 += __shfl_xor_sync(0xffffffffu, a3, m);
            }
            if (lane == 0) {
                gbuf[r0 + 0] = a0 + bias0;
                gbuf[r0 + 1] = a1 + bias1;
                gbuf[r0 + 2] = a2 + bias2;
                gbuf[r0 + 3] = a3 + bias3;
            }
        }
        __syncthreads();

        // -- elementwise LSTM update for this CTA's hidden slice --
        if (tid < J) {
            float ip = gbuf[tid];
            float fp = gbuf[J + tid];
            float gp = gbuf[2 * J + tid];
            float op = gbuf[3 * J + tid];
            float ig = sigmoidf_(ip);
            float fg = sigmoidf_(fp);
            float gg = tanhf(gp);
            float og = sigmoidf_(op);
            c_st = fg * c_st + ig * gg;
            float hn = og * tanhf(c_st);
            d_hs[(size_t)(t + 1) * HD + j0 + tid] = hn;
        }
        __syncthreads();

        if (tid == 0) {
            __threadfence();
            st_rel(&d_flags[b], t);
        }
    }
}

// ---------------------------------------------------------------------------
// Final projection: out[t] = [ hs[t]·W_uvw^T + b_uvw , hs[t]·W_pqr^T + b_pqr ]
// One warp per timestep.
// ---------------------------------------------------------------------------
extern "C" __global__ void __launch_bounds__(256)
proj_kernel(const float* __restrict__ Wuvw, const float* __restrict__ buvw,
            const float* __restrict__ Wpqr, const float* __restrict__ bpqr,
            float* __restrict__ out)
{
    int warp = threadIdx.x >> 5, lane = threadIdx.x & 31;
    int t = blockIdx.x * 8 + warp;
    if (t >= SEQ) return;

    const float4* h4 = (const float4*)(d_hs + (size_t)(t + 1) * HD);
    float a0 = 0.f, a1 = 0.f, a2 = 0.f, a3 = 0.f, a4 = 0.f, a5 = 0.f;

    #pragma unroll
    for (int k = 0; k < 16; ++k) {
        float4 hv = h4[lane + 32 * k];
        float4 w0 = __ldg((const float4*)(Wuvw + 0 * HD) + lane + 32 * k);
        float4 w1 = __ldg((const float4*)(Wuvw + 1 * HD) + lane + 32 * k);
        float4 w2 = __ldg((const float4*)(Wuvw + 2 * HD) + lane + 32 * k);
        float4 w3 = __ldg((const float4*)(Wpqr + 0 * HD) + lane + 32 * k);
        float4 w4 = __ldg((const float4*)(Wpqr + 1 * HD) + lane + 32 * k);
        float4 w5 = __ldg((const float4*)(Wpqr + 2 * HD) + lane + 32 * k);
        a0 += hv.x*w0.x + hv.y*w0.y + hv.z*w0.z + hv.w*w0.w;
        a1 += hv.x*w1.x + hv.y*w1.y + hv.z*w1.z + hv.w*w1.w;
        a2 += hv.x*w2.x + hv.y*w2.y + hv.z*w2.z + hv.w*w2.w;
        a3 += hv.x*w3.x + hv.y*w3.y + hv.z*w3.z + hv.w*w3.w;
        a4 += hv.x*w4.x + hv.y*w4.y + hv.z*w4.z + hv.w*w4.w;
        a5 += hv.x*w5.x + hv.y*w5.y + hv.z*w5.z + hv.w*w5.w;
    }
    #pragma unroll
    for (int m = 16; m >= 1; m >>= 1) {
        a0 += __shfl_xor_sync(0xffffffffu, a0, m);
        a1 += __shfl_xor_sync(0xffffffffu, a1, m);
        a2 += __shfl_xor_sync(0xffffffffu, a2, m);
        a3 += __shfl_xor_sync(0xffffffffu, a3, m);
        a4 += __shfl_xor_sync(0xffffffffu, a4, m);
        a5 += __shfl_xor_sync(0xffffffffu, a5, m);
    }
    if (lane == 0) {
        float* o = out + (size_t)t * 6;
        o[0] = a0 + __ldg(buvw + 0);
        o[1] = a1 + __ldg(buvw + 1);
        o[2] = a2 + __ldg(buvw + 2);
        o[3] = a3 + __ldg(bpqr + 0);
        o[4] = a4 + __ldg(bpqr + 1);
        o[5] = a5 + __ldg(bpqr + 2);
    }
}

// Reset h_0 = 0 and flags = -1 (stream-ordered before the persistent kernel).
extern "C" __global__ void reset_kernel()
{
    int i = blockIdx.x * blockDim.x + threadIdx.x;
    if (i < HD)   d_hs[i] = 0.0f;
    if (i < NCTA) d_flags[i] = -1;
}

extern "C" void kernel_launch(void* const* d_in, const int* in_sizes, int n_in,
                              void* d_out, int out_size)
{
    const float* sa   = (const float*)d_in[0];
    const float* Wih  = (const float*)d_in[1];
    const float* Whh  = (const float*)d_in[2];
    const float* bih  = (const float*)d_in[3];
    const float* bhh  = (const float*)d_in[4];
    const float* Wuvw = (const float*)d_in[5];
    const float* buvw = (const float*)d_in[6];
    const float* Wpqr = (const float*)d_in[7];
    const float* bpqr = (const float*)d_in[8];
    float* out = (float*)d_out;

    cudaFuncSetAttribute(lstm_persist,
                         cudaFuncAttributeMaxDynamicSharedMemorySize, SMEM_BYTES);

    reset_kernel<<<8, 256>>>();
    lstm_persist<<<NCTA, TPB, SMEM_BYTES>>>(sa, Wih, Whh, bih, bhh);
    proj_kernel<<<SEQ / 8, 256>>>(Wuvw, buvw, Wpqr, bpqr, out);
    (void)in_sizes; (void)n_in; (void)out_size;
}

// round 7
// speedup vs baseline: 1.9280x; 1.9280x over previous
#include <cuda_runtime.h>
#include <cuda_bf16.h>
#include <cstdint>
#include <cstddef>

#define HD        2048
#define SEQ       8192
#define IN_DIM    16
#define NCTA      147
#define JCAP      14              // hidden units per CTA (last CTA gets 4)
#define WARPS     14
#define TPB       (WARPS * 32)    // 448 threads
#define SMEM_COLS 1536            // weight columns kept in smem (k-chunks 0..11)
#define REG_K0    12              // k-chunks 12..15 register-resident
#define W_ROW_B   (SMEM_COLS * 2) // 3072 bytes per bf16 weight row
#define SMEM_BYTES (HD * 4 + 256 + 56 * W_ROW_B)   // 8192 + 256 + 172032 = 180480

// Persistent scratch (static __device__ globals — no allocation APIs).
__device__ float d_hs[(size_t)(SEQ + 1) * HD];  // h history, row 0 == h_0 == 0
__device__ int   d_cnt;                         // global arrival counter

__device__ __forceinline__ float blo(unsigned u) { return __uint_as_float(u << 16); }
__device__ __forceinline__ float bhi(unsigned u) { return __uint_as_float(u & 0xffff0000u); }

__device__ __forceinline__ int ld_acq(const int* p) {
    int v;
    asm volatile("ld.acquire.gpu.global.b32 %0, [%1];" : "=r"(v) : "l"(p));
    return v;
}
__device__ __forceinline__ void red_rel_add(int* p, int v) {
    asm volatile("red.release.gpu.global.add.s32 [%0], %1;" :: "l"(p), "r"(v) : "memory");
}

__device__ __forceinline__ float sigmoidf_(float x) {
    return 1.0f / (1.0f + __expf(-x));
}
__device__ __forceinline__ float tanh_fast(float x) {
    float xc = fminf(fmaxf(x, -15.0f), 15.0f);   // keep __expf finite
    float a = __expf(2.0f * xc);
    return (a - 1.0f) / (a + 1.0f);
}

// ---------------------------------------------------------------------------
// Persistent LSTM recurrence. CTA b owns hidden units [b*14, b*14+J).
// Its 4J gate rows of W_hh live on-chip (bf16): cols [0,1536) in SMEM,
// cols [1536,2048) in registers. h is staged fp32 in SMEM each step.
// Gate order (PyTorch): i, f, g, o  ->  local row r = g*J + jj.
// Grid barrier: one release-RED arrival per CTA into d_cnt; one poller
// thread per CTA acquires it (no poll storm), __syncthreads broadcasts.
// ---------------------------------------------------------------------------
extern "C" __global__ void __launch_bounds__(TPB, 1)
lstm_persist(const float* __restrict__ sa,  const float* __restrict__ Wih,
             const float* __restrict__ Whh, const float* __restrict__ bih,
             const float* __restrict__ bhh)
{
    extern __shared__ unsigned char smem[];
    float*          h_sm = (float*)smem;                       // 2048 f32
    float*          gbuf = (float*)(smem + HD * 4);            // 64 f32 gate staging
    __nv_bfloat16*  w_sm = (__nv_bfloat16*)(smem + HD * 4 + 256);

    const int tid  = threadIdx.x;
    const int w    = tid >> 5;
    const int lane = tid & 31;
    const int b    = blockIdx.x;
    const int j0   = b * JCAP;
    const int J    = (b == NCTA - 1) ? (HD - (NCTA - 1) * JCAP) : JCAP;  // 14 or 4
    const int R    = 4 * J;                                    // gate rows this CTA
    const int r0   = 4 * w;                                    // this warp's first local row
    const bool act = (r0 < R);

    // ---- one-time init: stage bf16 weights into SMEM (cols [0,1536)) ----
    for (int idx = tid; idx < R * SMEM_COLS; idx += TPB) {
        int r   = idx / SMEM_COLS;
        int col = idx - r * SMEM_COLS;
        int gr  = (r / J) * HD + j0 + (r % J);                 // global gate row
        w_sm[r * SMEM_COLS + col] = __float2bfloat16(Whh[(size_t)gr * HD + col]);
    }

    // ---- one-time init: register weights (cols [1536,2048)), xproj, biases ----
    unsigned wreg[4][4][2];
    float    wih_a = 0.f, wih_b = 0.f;
    float    bias0 = 0.f, bias1 = 0.f, bias2 = 0.f, bias3 = 0.f;
    #pragma unroll
    for (int i = 0; i < 4; ++i)
        #pragma unroll
        for (int k = 0; k < 4; ++k) { wreg[i][k][0] = 0u; wreg[i][k][1] = 0u; }

    if (act) {
        #pragma unroll
        for (int i = 0; i < 4; ++i) {
            int r  = r0 + i;
            int gr = (r / J) * HD + j0 + (r % J);
            const float* wr = Whh + (size_t)gr * HD;
            #pragma unroll
            for (int k = 0; k < 4; ++k) {
                int c = 4 * lane + 128 * (REG_K0 + k);
                __nv_bfloat162 p0 = __floats2bfloat162_rn(wr[c + 0], wr[c + 1]);
                __nv_bfloat162 p1 = __floats2bfloat162_rn(wr[c + 2], wr[c + 3]);
                wreg[i][k][0] = *(unsigned*)&p0;   // low 16 bits = even col
                wreg[i][k][1] = *(unsigned*)&p1;
            }
            float bi = __ldg(bih + gr) + __ldg(bhh + gr);
            if (i == 0) bias0 = bi; else if (i == 1) bias1 = bi;
            else if (i == 2) bias2 = bi; else bias3 = bi;
        }
        // x_proj coefficients: lanes 0..15 -> rows r0, r0+2 ; lanes 16..31 -> rows r0+1, r0+3
        int half = lane >> 4, m = lane & 15;
        int ra = r0 + half, rb = r0 + 2 + half;
        int gra = (ra / J) * HD + j0 + (ra % J);
        int grb = (rb / J) * HD + j0 + (rb % J);
        wih_a = __ldg(Wih + (size_t)gra * IN_DIM + m);
        wih_b = __ldg(Wih + (size_t)grb * IN_DIM + m);
    }

    // Per-row SMEM weight base pointers (lane-offset folded in).
    const uint2* wrow0 = (const uint2*)((const char*)w_sm + (size_t)(r0 + 0) * W_ROW_B + 8 * lane);
    const uint2* wrow1 = (const uint2*)((const char*)w_sm + (size_t)(r0 + 1) * W_ROW_B + 8 * lane);
    const uint2* wrow2 = (const uint2*)((const char*)w_sm + (size_t)(r0 + 2) * W_ROW_B + 8 * lane);
    const uint2* wrow3 = (const uint2*)((const char*)w_sm + (size_t)(r0 + 3) * W_ROW_B + 8 * lane);

    float c_st = 0.0f;   // cell state for unit (j0 + tid), threads tid < J
    int target = 0;      // arrivals required before step t can read h_t

    for (int t = 0; t < SEQ; ++t) {
        // -- x_proj for this warp's rows (independent of h): overlap with the wait --
        float va = 0.f, vb = 0.f, va1 = 0.f, vb1 = 0.f;
        if (act) {
            float sv = __ldg(sa + (size_t)t * IN_DIM + (lane & 15));
            va = wih_a * sv; vb = wih_b * sv;
            #pragma unroll
            for (int m = 1; m <= 8; m <<= 1) {
                va += __shfl_xor_sync(0xffffffffu, va, m);
                vb += __shfl_xor_sync(0xffffffffu, vb, m);
            }
            va1 = __shfl_sync(0xffffffffu, va, 16);   // row r0+1 value, to lane 0
            vb1 = __shfl_sync(0xffffffffu, vb, 16);   // row r0+3 value, to lane 0
        }

        // -- single-poller grid barrier: wait until all CTAs published h_t --
        if (tid == 0) { while (ld_acq(&d_cnt) < target) { } }
        __syncthreads();

        // -- stage h_t into SMEM (fp32, L2-coherent loads) --
        {
            const float4* hrow = (const float4*)(d_hs + (size_t)t * HD);
            for (int i = tid; i < HD / 4; i += TPB)
                ((float4*)h_sm)[i] = __ldcg(hrow + i);
        }
        __syncthreads();

        if (act) {
            float a0 = 0.f, a1 = 0.f, a2 = 0.f, a3 = 0.f;
            const float4* h4 = (const float4*)h_sm;

            #pragma unroll
            for (int k = 0; k < REG_K0; ++k) {           // SMEM weight chunks
                float4 hv = h4[lane + 32 * k];
                uint2 p;
                p = wrow0[32 * k];
                a0 = fmaf(blo(p.x), hv.x, a0); a0 = fmaf(bhi(p.x), hv.y, a0);
                a0 = fmaf(blo(p.y), hv.z, a0); a0 = fmaf(bhi(p.y), hv.w, a0);
                p = wrow1[32 * k];
                a1 = fmaf(blo(p.x), hv.x, a1); a1 = fmaf(bhi(p.x), hv.y, a1);
                a1 = fmaf(blo(p.y), hv.z, a1); a1 = fmaf(bhi(p.y), hv.w, a1);
                p = wrow2[32 * k];
                a2 = fmaf(blo(p.x), hv.x, a2); a2 = fmaf(bhi(p.x), hv.y, a2);
                a2 = fmaf(blo(p.y), hv.z, a2); a2 = fmaf(bhi(p.y), hv.w, a2);
                p = wrow3[32 * k];
                a3 = fmaf(blo(p.x), hv.x, a3); a3 = fmaf(bhi(p.x), hv.y, a3);
                a3 = fmaf(blo(p.y), hv.z, a3); a3 = fmaf(bhi(p.y), hv.w, a3);
            }
            #pragma unroll
            for (int k = 0; k < 4; ++k) {                // register weight chunks
                float4 hv = h4[lane + 32 * (REG_K0 + k)];
                unsigned u, v;
                u = wreg[0][k][0]; v = wreg[0][k][1];
                a0 = fmaf(blo(u), hv.x, a0); a0 = fmaf(bhi(u), hv.y, a0);
                a0 = fmaf(blo(v), hv.z, a0); a0 = fmaf(bhi(v), hv.w, a0);
                u = wreg[1][k][0]; v = wreg[1][k][1];
                a1 = fmaf(blo(u), hv.x, a1); a1 = fmaf(bhi(u), hv.y, a1);
                a1 = fmaf(blo(v), hv.z, a1); a1 = fmaf(bhi(v), hv.w, a1);
                u = wreg[2][k][0]; v = wreg[2][k][1];
                a2 = fmaf(blo(u), hv.x, a2); a2 = fmaf(bhi(u), hv.y, a2);
                a2 = fmaf(blo(v), hv.z, a2); a2 = fmaf(bhi(v), hv.w, a2);
                u = wreg[3][k][0]; v = wreg[3][k][1];
                a3 = fmaf(blo(u), hv.x, a3); a3 = fmaf(bhi(u), hv.y, a3);
                a3 = fmaf(blo(v), hv.z, a3); a3 = fmaf(bhi(v), hv.w, a3);
            }

            #pragma unroll
            for (int m = 16; m >= 1; m >>= 1) {
                a0 += __shfl_xor_sync(0xffffffffu, a0, m);
                a1 += __shfl_xor_sync(0xffffffffu, a1, m);
                a2 += __shfl_xor_sync(0xffffffffu, a2, m);
                a3 += __shfl_xor_sync(0xffffffffu, a3, m);
            }
            if (lane == 0) {
                gbuf[r0 + 0] = a0 + bias0 + va;
                gbuf[r0 + 1] = a1 + bias1 + va1;
                gbuf[r0 + 2] = a2 + bias2 + vb;
                gbuf[r0 + 3] = a3 + bias3 + vb1;
            }
        }
        __syncthreads();

        // -- elementwise LSTM update for this CTA's hidden slice --
        if (tid < J) {
            float ip = gbuf[tid];
            float fp = gbuf[J + tid];
            float gp = gbuf[2 * J + tid];
            float op = gbuf[3 * J + tid];
            float ig = sigmoidf_(ip);
            float fg = sigmoidf_(fp);
            float gg = tanh_fast(gp);
            float og = sigmoidf_(op);
            c_st = fg * c_st + ig * gg;
            float hn = og * tanh_fast(c_st);
            d_hs[(size_t)(t + 1) * HD + j0 + tid] = hn;
        }
        __syncthreads();

        if (tid == 0) {
            __threadfence();            // make h stores visible before arrival
            red_rel_add(&d_cnt, 1);     // fire-and-forget arrival
        }
        target += NCTA;
    }
}

// ---------------------------------------------------------------------------
// Final projection: out[t] = [ hs[t]·W_uvw^T + b_uvw , hs[t]·W_pqr^T + b_pqr ]
// One warp per timestep.
// ---------------------------------------------------------------------------
extern "C" __global__ void __launch_bounds__(256)
proj_kernel(const float* __restrict__ Wuvw, const float* __restrict__ buvw,
            const float* __restrict__ Wpqr, const float* __restrict__ bpqr,
            float* __restrict__ out)
{
    int warp = threadIdx.x >> 5, lane = threadIdx.x & 31;
    int t = blockIdx.x * 8 + warp;
    if (t >= SEQ) return;

    const float4* h4 = (const float4*)(d_hs + (size_t)(t + 1) * HD);
    float a0 = 0.f, a1 = 0.f, a2 = 0.f, a3 = 0.f, a4 = 0.f, a5 = 0.f;

    #pragma unroll
    for (int k = 0; k < 16; ++k) {
        float4 hv = h4[lane + 32 * k];
        float4 w0 = __ldg((const float4*)(Wuvw + 0 * HD) + lane + 32 * k);
        float4 w1 = __ldg((const float4*)(Wuvw + 1 * HD) + lane + 32 * k);
        float4 w2 = __ldg((const float4*)(Wuvw + 2 * HD) + lane + 32 * k);
        float4 w3 = __ldg((const float4*)(Wpqr + 0 * HD) + lane + 32 * k);
        float4 w4 = __ldg((const float4*)(Wpqr + 1 * HD) + lane + 32 * k);
        float4 w5 = __ldg((const float4*)(Wpqr + 2 * HD) + lane + 32 * k);
        a0 += hv.x*w0.x + hv.y*w0.y + hv.z*w0.z + hv.w*w0.w;
        a1 += hv.x*w1.x + hv.y*w1.y + hv.z*w1.z + hv.w*w1.w;
        a2 += hv.x*w2.x + hv.y*w2.y + hv.z*w2.z + hv.w*w2.w;
        a3 += hv.x*w3.x + hv.y*w3.y + hv.z*w3.z + hv.w*w3.w;
        a4 += hv.x*w4.x + hv.y*w4.y + hv.z*w4.z + hv.w*w4.w;
        a5 += hv.x*w5.x + hv.y*w5.y + hv.z*w5.z + hv.w*w5.w;
    }
    #pragma unroll
    for (int m = 16; m >= 1; m >>= 1) {
        a0 += __shfl_xor_sync(0xffffffffu, a0, m);
        a1 += __shfl_xor_sync(0xffffffffu, a1, m);
        a2 += __shfl_xor_sync(0xffffffffu, a2, m);
        a3 += __shfl_xor_sync(0xffffffffu, a3, m);
        a4 += __shfl_xor_sync(0xffffffffu, a4, m);
        a5 += __shfl_xor_sync(0xffffffffu, a5, m);
    }
    if (lane == 0) {
        float* o = out + (size_t)t * 6;
        o[0] = a0 + __ldg(buvw + 0);
        o[1] = a1 + __ldg(buvw + 1);
        o[2] = a2 + __ldg(buvw + 2);
        o[3] = a3 + __ldg(bpqr + 0);
        o[4] = a4 + __ldg(bpqr + 1);
        o[5] = a5 + __ldg(bpqr + 2);
    }
}

// Reset h_0 = 0 and d_cnt = 0 (stream-ordered before the persistent kernel).
extern "C" __global__ void reset_kernel()
{
    int i = blockIdx.x * blockDim.x + threadIdx.x;
    if (i < HD) d_hs[i] = 0.0f;
    if (i == 0) d_cnt = 0;
}

extern "C" void kernel_launch(void* const* d_in, const int* in_sizes, int n_in,
                              void* d_out, int out_size)
{
    const float* sa   = (const float*)d_in[0];
    const float* Wih  = (const float*)d_in[1];
    const float* Whh  = (const float*)d_in[2];
    const float* bih  = (const float*)d_in[3];
    const float* bhh  = (const float*)d_in[4];
    const float* Wuvw = (const float*)d_in[5];
    const float* buvw = (const float*)d_in[6];
    const float* Wpqr = (const float*)d_in[7];
    const float* bpqr = (const float*)d_in[8];
    float* out = (float*)d_out;

    cudaFuncSetAttribute(lstm_persist,
                         cudaFuncAttributeMaxDynamicSharedMemorySize, SMEM_BYTES);

    reset_kernel<<<8, 256>>>();
    lstm_persist<<<NCTA, TPB, SMEM_BYTES>>>(sa, Wih, Whh, bih, bhh);
    proj_kernel<<<SEQ / 8, 256>>>(Wuvw, buvw, Wpqr, bpqr, out);
    (void)in_sizes; (void)n_in; (void)out_size;
}